// round 2
// baseline (speedup 1.0000x reference)
#include <cuda_runtime.h>
#include <math.h>

#define BB 16
#define SS 1024
#define DD 1024
#define CH 16
#define RR 256            // CH*BB rows per chunk
#define NC 64             // SS/CH chunks
#define SB (SS*BB)        // 16384 rows total
#define ETA_F (0.01f*2.0f/(16.0f*1024.0f))

// ---------------- device scratch (no allocations allowed) ----------------
__device__ float g_HT[SB*DD];      // tanh(alpha1*x), time-major rows r=t*B+b
__device__ float g_STATE[SB*DD];   // HT @ Ws^T
__device__ float g_TV[SB*DD];      // STATE + noise
__device__ float g_PROBE[SB*DD];   // HT @ Wp^T
__device__ float g_OT[SB*DD];      // ttt readout, time-major
__device__ float g_X1[SB*DD];      // x1 = ttt + x, b-major
__device__ float g_H2[SB*DD];      // tanh(alpha2*x1), b-major
__device__ float g_U[SB*DD];       // gelu(h2 @ Wp1^T), b-major
__device__ float g_W[DD*DD];       // evolving mapping weight
__device__ float g_AP[2*RR*DD];    // per-chunk: rows 0..255 = A, 256..511 = P0
__device__ float g_E[RR*DD];       // per-chunk solved E
__device__ float g_Gb[NC*RR*RR];   // batched Gram TV_c TV_c^T
__device__ float g_Hb[NC*RR*RR];   // batched PROBE_c TV_c^T (block-tril masked)

// ---------------- elementwise kernels ----------------
__global__ void k_prep(const float* __restrict__ x, const float* __restrict__ a1,
                       float* __restrict__ HT) {
    long i4 = (long)blockIdx.x * blockDim.x + threadIdx.x;   // over SB*DD/4
    long flat = i4 * 4;
    int b = (int)(flat / ((long)SS*DD));
    int t = (int)((flat / DD) % SS);
    int d = (int)(flat % DD);
    float4 xv = *(const float4*)(x + flat);
    float4 av = *(const float4*)(a1 + d);
    float4 o;
    o.x = tanhf(av.x * xv.x); o.y = tanhf(av.y * xv.y);
    o.z = tanhf(av.z * xv.z); o.w = tanhf(av.w * xv.w);
    *(float4*)(HT + ((long)(t*BB + b) * DD + d)) = o;
}

__global__ void k_tv(const float* __restrict__ ST, const float* __restrict__ noise,
                     float* __restrict__ TV) {
    long i4 = (long)blockIdx.x * blockDim.x + threadIdx.x;
    long flat = i4 * 4;                       // time-major flat index
    int t = (int)(flat / ((long)BB*DD));
    int b = (int)((flat / DD) % BB);
    int d = (int)(flat % DD);
    float4 s = *(const float4*)(ST + flat);
    float4 n = *(const float4*)(noise + ((long)b*SS + t) * DD + d);
    float4 o; o.x = s.x+n.x; o.y = s.y+n.y; o.z = s.z+n.z; o.w = s.w+n.w;
    *(float4*)(TV + flat) = o;
}

__global__ void k_copyW(const float* __restrict__ src, float* __restrict__ dst) {
    long i4 = (long)blockIdx.x * blockDim.x + threadIdx.x;
    *(float4*)(dst + i4*4) = *(const float4*)(src + i4*4);
}

__global__ void k_x1h2(const float* __restrict__ OT, const float* __restrict__ x,
                       const float* __restrict__ a2,
                       float* __restrict__ X1, float* __restrict__ H2) {
    long i4 = (long)blockIdx.x * blockDim.x + threadIdx.x;
    long flat = i4 * 4;                       // b-major
    int b = (int)(flat / ((long)SS*DD));
    int t = (int)((flat / DD) % SS);
    int d = (int)(flat % DD);
    float4 ro = *(const float4*)(OT + ((long)(t*BB + b) * DD + d));
    float4 xv = *(const float4*)(x + flat);
    float4 av = *(const float4*)(a2 + d);
    float4 x1; x1.x = ro.x+xv.x; x1.y = ro.y+xv.y; x1.z = ro.z+xv.z; x1.w = ro.w+xv.w;
    *(float4*)(X1 + flat) = x1;
    float4 h; h.x = tanhf(av.x*x1.x); h.y = tanhf(av.y*x1.y);
    h.z = tanhf(av.z*x1.z); h.w = tanhf(av.w*x1.w);
    *(float4*)(H2 + flat) = h;
}

// ---------------- forward-substitution solve (per chunk) ----------------
// E_t = A_t - ETA * sum_{s<t} G[t,s] @ E_s  (16x16 blocks, C=16 steps)
// grid: 64 CTAs x 16 columns each; 256 threads = (row 0..15, col 0..15)
__global__ void __launch_bounds__(256) solve_k(const float* __restrict__ A,
                                               const float* __restrict__ G,
                                               float* __restrict__ E) {
    __shared__ float Es[RR][17];
    const int j0 = blockIdx.x * 16;
    const int tid = threadIdx.x;
    const int r = tid >> 4, j = tid & 15;
    #pragma unroll
    for (int i = 0; i < 16; ++i) {
        int row = i*16 + r;
        Es[row][j] = A[(long)row * DD + j0 + j];
    }
    __syncthreads();
    for (int t = 1; t < 16; ++t) {
        const float* Gr = G + (long)(t*16 + r) * RR;
        const int kmax = t * 16;
        float acc = 0.f;
        #pragma unroll 8
        for (int k = 0; k < kmax; ++k) acc += Gr[k] * Es[k][j];
        float v = Es[t*16 + r][j] - ETA_F * acc;
        Es[t*16 + r][j] = v;  // writes rows >= 16t, reads were rows < 16t: disjoint
        __syncthreads();
    }
    #pragma unroll
    for (int i = 0; i < 16; ++i) {
        int row = i*16 + r;
        E[(long)row * DD + j0 + j] = Es[row][j];
    }
}

// ---------------- generic tiled fp32 GEMM ----------------
// OPA: 0 = A[M,K] row-major; 1 = A stored [K,M] (A^T op); 2 = dual-source rows
//      (rows < RR from A, rows >= RR from A2), both row-major [.,K]
// OPB: 0 = C += A*B^T with B[N,K]; 1 = C += A*B with B[K,N]
// MODE: 0 plain  1 AP(sub STATE on rows<RR)  2 block-tril mask  3 readout
//       4 W in-place update  5 gelu  6 final (U*acc + X1)
template<int BM,int BN,int BK,int TM,int TN,int OPA,int OPB,int MODE>
__global__ void __launch_bounds__(256)
gemm_k(const float* __restrict__ A, const float* __restrict__ A2, int lda,
       const float* __restrict__ B, int ldb,
       float* __restrict__ C, int ldc,
       int M, int N, int K,
       const float* __restrict__ P1, const float* __restrict__ P2,
       long saz, long sbz, long scz)
{
    const int bz = blockIdx.z;
    A += (long)bz * saz;
    B += (long)bz * sbz;
    C += (long)bz * scz;
    const int m0 = blockIdx.y * BM, n0 = blockIdx.x * BN;

    __shared__ float As[BK][BM+4];
    __shared__ float Bs[BK][BN+4];

    const int tid = threadIdx.x;
    const int tx = tid & 15, ty = tid >> 4;

    float acc[TM][TN];
    #pragma unroll
    for (int i = 0; i < TM; ++i)
        #pragma unroll
        for (int j = 0; j < TN; ++j) acc[i][j] = 0.f;

    int Kl = K;
    if (MODE == 3) { int kl = m0 + BM; Kl = kl < K ? kl : K; }  // tril: skip zero tiles
    const int ktiles = Kl / BK;

    float4 ra, rb;

    auto loadA = [&](int k0) {
        if (OPA == 1) {
            const int amq = tid % (BM/4), ak = tid / (BM/4);
            ra = *(const float4*)(A + (long)(k0 + ak) * lda + m0 + 4*amq);
        } else {
            const int akq = tid % (BK/4), am = tid / (BK/4);
            const int mg = m0 + am;
            const float* Ar;
            if (OPA == 2) Ar = (mg < RR) ? (A + (long)mg * lda)
                                         : (A2 + (long)(mg - RR) * lda);
            else          Ar = A + (long)mg * lda;
            ra = *(const float4*)(Ar + k0 + 4*akq);
        }
    };
    auto storeA = [&]() {
        if (OPA == 1) {
            const int amq = tid % (BM/4), ak = tid / (BM/4);
            *(float4*)&As[ak][4*amq] = ra;
        } else {
            const int akq = tid % (BK/4), am = tid / (BK/4);
            As[4*akq+0][am] = ra.x; As[4*akq+1][am] = ra.y;
            As[4*akq+2][am] = ra.z; As[4*akq+3][am] = ra.w;
        }
    };
    auto loadB = [&](int k0) {
        if (OPB == 1) {
            const int bnq = tid % (BN/4), bk = tid / (BN/4);
            rb = *(const float4*)(B + (long)(k0 + bk) * ldb + n0 + 4*bnq);
        } else {
            const int bkq = tid % (BK/4), bn = tid / (BK/4);
            rb = *(const float4*)(B + (long)(n0 + bn) * ldb + k0 + 4*bkq);
        }
    };
    auto storeB = [&]() {
        if (OPB == 1) {
            const int bnq = tid % (BN/4), bk = tid / (BN/4);
            *(float4*)&Bs[bk][4*bnq] = rb;
        } else {
            const int bkq = tid % (BK/4), bn = tid / (BK/4);
            Bs[4*bkq+0][bn] = rb.x; Bs[4*bkq+1][bn] = rb.y;
            Bs[4*bkq+2][bn] = rb.z; Bs[4*bkq+3][bn] = rb.w;
        }
    };

    loadA(0); loadB(0);
    storeA(); storeB();
    __syncthreads();

    for (int kt = 0; kt < ktiles; ++kt) {
        const bool more = (kt + 1 < ktiles);
        if (more) { loadA((kt+1)*BK); loadB((kt+1)*BK); }

        #pragma unroll
        for (int kk = 0; kk < BK; ++kk) {
            float af[TM], bf[TN];
            #pragma unroll
            for (int i = 0; i < TM; i += 4) {
                float4 v = *(const float4*)&As[kk][ty*TM + i];
                af[i] = v.x; af[i+1] = v.y; af[i+2] = v.z; af[i+3] = v.w;
            }
            #pragma unroll
            for (int j = 0; j < TN; j += 4) {
                float4 v = *(const float4*)&Bs[kk][tx*TN + j];
                bf[j] = v.x; bf[j+1] = v.y; bf[j+2] = v.z; bf[j+3] = v.w;
            }
            #pragma unroll
            for (int i = 0; i < TM; ++i)
                #pragma unroll
                for (int j = 0; j < TN; ++j)
                    acc[i][j] = fmaf(af[i], bf[j], acc[i][j]);
        }
        __syncthreads();
        if (more) { storeA(); storeB(); __syncthreads(); }
    }

    #pragma unroll
    for (int i = 0; i < TM; ++i) {
        const int m = m0 + ty*TM + i;
        #pragma unroll
        for (int j = 0; j < TN; ++j) {
            const int n = n0 + tx*TN + j;
            const long ci = (long)m * ldc + n;
            float v = acc[i][j];
            if (MODE == 0) {
                C[ci] = v;
            } else if (MODE == 1) {
                if (m < RR) v -= P1[(long)m * ldc + n];
                C[ci] = v;
            } else if (MODE == 2) {
                C[ci] = ((n >> 4) > (m >> 4)) ? 0.f : v;
            } else if (MODE == 3) {
                C[ci] = P1[(long)m * DD + n] - ETA_F * v;
            } else if (MODE == 4) {
                C[ci] = C[ci] - ETA_F * v;
            } else if (MODE == 5) {
                C[ci] = 0.5f * v * (1.f + erff(v * 0.70710678118654752f));
            } else if (MODE == 6) {
                C[ci] = P1[ci] * v + P2[ci];
            }
        }
    }
}

// ---------------- host side ----------------
extern "C" void kernel_launch(void* const* d_in, const int* in_sizes, int n_in,
                              void* d_out, int out_size) {
    const float* x      = (const float*)d_in[0];
    const float* noise  = (const float*)d_in[1];
    const float* alpha1 = (const float*)d_in[2];
    const float* alpha2 = (const float*)d_in[3];
    const float* W_map  = (const float*)d_in[4];
    const float* W_st   = (const float*)d_in[5];
    const float* W_pr   = (const float*)d_in[6];
    const float* W_p1   = (const float*)d_in[7];
    const float* W_p2   = (const float*)d_in[8];
    float* out = (float*)d_out;

    float *HT, *ST, *TV, *PR, *OT, *X1, *H2, *U, *W, *AP, *E, *Gb, *Hb;
    cudaGetSymbolAddress((void**)&HT, g_HT);
    cudaGetSymbolAddress((void**)&ST, g_STATE);
    cudaGetSymbolAddress((void**)&TV, g_TV);
    cudaGetSymbolAddress((void**)&PR, g_PROBE);
    cudaGetSymbolAddress((void**)&OT, g_OT);
    cudaGetSymbolAddress((void**)&X1, g_X1);
    cudaGetSymbolAddress((void**)&H2, g_H2);
    cudaGetSymbolAddress((void**)&U,  g_U);
    cudaGetSymbolAddress((void**)&W,  g_W);
    cudaGetSymbolAddress((void**)&AP, g_AP);
    cudaGetSymbolAddress((void**)&E,  g_E);
    cudaGetSymbolAddress((void**)&Gb, g_Gb);
    cudaGetSymbolAddress((void**)&Hb, g_Hb);

    const int EW_BLKS = (SB*DD/4) / 256;   // 16384

    // 1. h = tanh(alpha1*x), time-major
    k_prep<<<EW_BLKS, 256>>>(x, alpha1, HT);
    // 2. STATE = HT @ Ws^T ; PROBE = HT @ Wp^T   (big NT GEMMs)
    gemm_k<128,128,8,8,8,0,0,0><<<dim3(DD/128, SB/128, 1), 256>>>(
        HT, nullptr, DD, W_st, DD, ST, DD, SB, DD, DD, nullptr, nullptr, 0,0,0);
    gemm_k<128,128,8,8,8,0,0,0><<<dim3(DD/128, SB/128, 1), 256>>>(
        HT, nullptr, DD, W_pr, DD, PR, DD, SB, DD, DD, nullptr, nullptr, 0,0,0);
    // 3. TV = STATE + noise
    k_tv<<<EW_BLKS, 256>>>(ST, noise, TV);
    // 4. W = W_map
    k_copyW<<<(DD*DD/4)/256, 256>>>(W_map, W);
    // 5. batched Gram matrices for all chunks (W-independent)
    gemm_k<64,64,16,4,4,0,0,0><<<dim3(RR/64, RR/64, NC), 256>>>(
        TV, nullptr, DD, TV, DD, Gb, RR, RR, RR, DD, nullptr, nullptr,
        (long)RR*DD, (long)RR*DD, (long)RR*RR);
    gemm_k<64,64,16,4,4,0,0,2><<<dim3(RR/64, RR/64, NC), 256>>>(
        PR, nullptr, DD, TV, DD, Hb, RR, RR, RR, DD, nullptr, nullptr,
        (long)RR*DD, (long)RR*DD, (long)RR*RR);

    // 6. sequential chunk loop
    for (int c = 0; c < NC; ++c) {
        const float* TVc = TV + (long)c*RR*DD;
        const float* PRc = PR + (long)c*RR*DD;
        const float* STc = ST + (long)c*RR*DD;
        // A = TVc@W^T - STATEc (rows 0..255) ; P0 = PRc@W^T (rows 256..511)
        gemm_k<64,64,16,4,4,2,0,1><<<dim3(DD/64, (2*RR)/64, 1), 256>>>(
            TVc, PRc, DD, W, DD, AP, DD, 2*RR, DD, DD, STc, nullptr, 0,0,0);
        // forward substitution -> E
        solve_k<<<DD/16, 256>>>(AP, Gb + (long)c*RR*RR, E);
        // readout = P0 - ETA * trilH @ E  -> OT chunk rows
        gemm_k<64,64,16,4,4,0,1,3><<<dim3(DD/64, RR/64, 1), 256>>>(
            Hb + (long)c*RR*RR, nullptr, RR, E, DD,
            OT + (long)c*RR*DD, DD, RR, DD, RR,
            AP + (long)RR*DD, nullptr, 0,0,0);
        // W -= ETA * E^T @ TVc
        gemm_k<64,64,16,4,4,1,1,4><<<dim3(DD/64, DD/64, 1), 256>>>(
            E, nullptr, DD, TVc, DD, W, DD, DD, DD, RR, nullptr, nullptr, 0,0,0);
    }

    // 7. x1 = ttt + x ; h2 = tanh(alpha2*x1)
    k_x1h2<<<EW_BLKS, 256>>>(OT, x, alpha2, X1, H2);
    // 8. U = gelu(h2 @ Wp1^T)
    gemm_k<128,128,8,8,8,0,0,5><<<dim3(DD/128, SB/128, 1), 256>>>(
        H2, nullptr, DD, W_p1, DD, U, DD, SB, DD, DD, nullptr, nullptr, 0,0,0);
    // 9. out = U * (h2 @ Wp2^T) + X1
    gemm_k<128,128,8,8,8,0,0,6><<<dim3(DD/128, SB/128, 1), 256>>>(
        H2, nullptr, DD, W_p2, DD, out, DD, SB, DD, DD, U, X1, 0,0,0);
}

// round 3
// speedup vs baseline: 1.3119x; 1.3119x over previous
#include <cuda_runtime.h>
#include <math.h>

#define BB 16
#define SS 1024
#define DD 1024
#define CH 16
#define RR 256            // CH*BB rows per chunk
#define NC 64             // SS/CH chunks
#define SB (SS*BB)        // 16384 rows total
#define ETA_F (0.01f*2.0f/(16.0f*1024.0f))

// ---------------- device scratch ----------------
__device__ float g_HT[SB*DD];
__device__ float g_STATE[SB*DD];
__device__ float g_TV[SB*DD];
__device__ float g_PROBE[SB*DD];
__device__ float g_OT[SB*DD];
__device__ float g_X1[SB*DD];
__device__ float g_H2[SB*DD];
__device__ float g_U[SB*DD];
__device__ float g_W[DD*DD];
__device__ float g_AP[2*RR*DD];
__device__ float g_E[RR*DD];
__device__ float g_Gb[NC*RR*RR];
__device__ float g_Hb[NC*RR*RR];

// ---------------- helpers ----------------
__device__ __forceinline__ float tf32r(float x) {
    unsigned u;
    asm("cvt.rna.tf32.f32 %0, %1;" : "=r"(u) : "f"(x));
    return __uint_as_float(u);
}

__device__ __forceinline__ void mma_tf32(float* c, const unsigned* a, const unsigned* b) {
    asm volatile(
        "mma.sync.aligned.m16n8k8.row.col.f32.tf32.tf32.f32 "
        "{%0,%1,%2,%3}, {%4,%5,%6,%7}, {%8,%9}, {%0,%1,%2,%3};\n"
        : "+f"(c[0]), "+f"(c[1]), "+f"(c[2]), "+f"(c[3])
        : "r"(a[0]), "r"(a[1]), "r"(a[2]), "r"(a[3]), "r"(b[0]), "r"(b[1]));
}

// ---------------- elementwise kernels ----------------
__global__ void k_prep(const float* __restrict__ x, const float* __restrict__ a1,
                       float* __restrict__ HT) {
    long i4 = (long)blockIdx.x * blockDim.x + threadIdx.x;
    long flat = i4 * 4;
    int b = (int)(flat / ((long)SS*DD));
    int t = (int)((flat / DD) % SS);
    int d = (int)(flat % DD);
    float4 xv = *(const float4*)(x + flat);
    float4 av = *(const float4*)(a1 + d);
    float4 o;
    o.x = tanhf(av.x * xv.x); o.y = tanhf(av.y * xv.y);
    o.z = tanhf(av.z * xv.z); o.w = tanhf(av.w * xv.w);
    *(float4*)(HT + ((long)(t*BB + b) * DD + d)) = o;
}

__global__ void k_tv(const float* __restrict__ ST, const float* __restrict__ noise,
                     float* __restrict__ TV) {
    long i4 = (long)blockIdx.x * blockDim.x + threadIdx.x;
    long flat = i4 * 4;
    int t = (int)(flat / ((long)BB*DD));
    int b = (int)((flat / DD) % BB);
    int d = (int)(flat % DD);
    float4 s = *(const float4*)(ST + flat);
    float4 n = *(const float4*)(noise + ((long)b*SS + t) * DD + d);
    float4 o; o.x = s.x+n.x; o.y = s.y+n.y; o.z = s.z+n.z; o.w = s.w+n.w;
    *(float4*)(TV + flat) = o;
}

__global__ void k_copyW(const float* __restrict__ src, float* __restrict__ dst) {
    long i4 = (long)blockIdx.x * blockDim.x + threadIdx.x;
    *(float4*)(dst + i4*4) = *(const float4*)(src + i4*4);
}

__global__ void k_x1h2(const float* __restrict__ OT, const float* __restrict__ x,
                       const float* __restrict__ a2,
                       float* __restrict__ X1, float* __restrict__ H2) {
    long i4 = (long)blockIdx.x * blockDim.x + threadIdx.x;
    long flat = i4 * 4;
    int b = (int)(flat / ((long)SS*DD));
    int t = (int)((flat / DD) % SS);
    int d = (int)(flat % DD);
    float4 ro = *(const float4*)(OT + ((long)(t*BB + b) * DD + d));
    float4 xv = *(const float4*)(x + flat);
    float4 av = *(const float4*)(a2 + d);
    float4 x1; x1.x = ro.x+xv.x; x1.y = ro.y+xv.y; x1.z = ro.z+xv.z; x1.w = ro.w+xv.w;
    *(float4*)(X1 + flat) = x1;
    float4 h; h.x = tanhf(av.x*x1.x); h.y = tanhf(av.y*x1.y);
    h.z = tanhf(av.z*x1.z); h.w = tanhf(av.w*x1.w);
    *(float4*)(H2 + flat) = h;
}

// ---------------- forward substitution (unchanged, validated) ----------------
__global__ void __launch_bounds__(256) solve_k(const float* __restrict__ A,
                                               const float* __restrict__ G,
                                               float* __restrict__ E) {
    __shared__ float Es[RR][17];
    const int j0 = blockIdx.x * 16;
    const int tid = threadIdx.x;
    const int r = tid >> 4, j = tid & 15;
    #pragma unroll
    for (int i = 0; i < 16; ++i) {
        int row = i*16 + r;
        Es[row][j] = A[(long)row * DD + j0 + j];
    }
    __syncthreads();
    for (int t = 1; t < 16; ++t) {
        const float* Gr = G + (long)(t*16 + r) * RR;
        const int kmax = t * 16;
        float acc = 0.f;
        #pragma unroll 8
        for (int k = 0; k < kmax; ++k) acc += Gr[k] * Es[k][j];
        float v = Es[t*16 + r][j] - ETA_F * acc;
        Es[t*16 + r][j] = v;
        __syncthreads();
    }
    #pragma unroll
    for (int i = 0; i < 16; ++i) {
        int row = i*16 + r;
        E[(long)row * DD + j0 + j] = Es[row][j];
    }
}

// ---------------- tf32 tensor-core GEMM ----------------
// OPA: 0 = A[M,K] row-major; 1 = A stored [K,M] (A^T); 2 = dual-source rows
// OPB: 0 = C = A*B^T, B[N,K] row-major; 1 = C = A*B, B[K,N] row-major
// MODE: 0 plain  1 sub P1 on rows<RR  2 block-tril mask  3 C=P1-ETA*acc
//       4 C-=ETA*acc  5 gelu  6 C=P1*acc+P2
template<int BM,int BN,int MW,int NW,int OPA,int OPB,int MODE>
__global__ void __launch_bounds__(MW*NW*32)
gemm_t(const float* __restrict__ A, const float* __restrict__ A2, int lda,
       const float* __restrict__ B, int ldb,
       float* __restrict__ C, int ldc,
       int M, int N, int K,
       const float* __restrict__ P1, const float* __restrict__ P2,
       long saz, long sbz, long scz)
{
    constexpr int BK = 16;
    constexpr int T  = MW*NW*32;
    constexpr int WM = BM/MW, WN = BN/NW;
    constexpr int MT = WM/16, NT = WN/8;
    constexpr int LA = BM + 4, LB = BN + 4;

    const int bz = blockIdx.z;
    A += (long)bz * saz;
    B += (long)bz * sbz;
    C += (long)bz * scz;
    const int m0 = blockIdx.y * BM, n0 = blockIdx.x * BN;

    __shared__ float As[BK][LA];
    __shared__ float Bs[BK][LB];

    const int tid  = threadIdx.x;
    const int lane = tid & 31;
    const int wid  = tid >> 5;
    const int wm   = wid / NW, wn = wid % NW;
    const int mw0  = wm * WM, nw0 = wn * WN;
    const int qr   = lane >> 2;   // 0..7
    const int qc   = lane & 3;    // 0..3

    float acc[MT][NT][4];
    #pragma unroll
    for (int i = 0; i < MT; ++i)
        #pragma unroll
        for (int j = 0; j < NT; ++j)
            #pragma unroll
            for (int q = 0; q < 4; ++q) acc[i][j][q] = 0.f;

    int Kl = K;
    if (MODE == 3) { int kl = m0 + BM; Kl = kl < K ? kl : K; }
    const int ktiles = Kl / BK;

    float4 pa[2], pb[2];

    auto gload = [&](int k0) {
        #pragma unroll
        for (int p = 0; p < 2; ++p) {
            const int idx = tid + p*T;
            if (OPA == 1) {
                const int ak = idx / (BM/4), amq = idx % (BM/4);
                pa[p] = *(const float4*)(A + (long)(k0 + ak) * lda + m0 + 4*amq);
            } else {
                const int am = idx / (BK/4), akq = idx % (BK/4);
                const int mg = m0 + am;
                const float* Ar;
                if (OPA == 2) Ar = (mg < RR) ? (A + (long)mg * lda)
                                             : (A2 + (long)(mg - RR) * lda);
                else          Ar = A + (long)mg * lda;
                pa[p] = *(const float4*)(Ar + k0 + 4*akq);
            }
            if (OPB == 1) {
                const int bk = idx / (BN/4), bnq = idx % (BN/4);
                pb[p] = *(const float4*)(B + (long)(k0 + bk) * ldb + n0 + 4*bnq);
            } else {
                const int bn = idx / (BK/4), bkq = idx % (BK/4);
                pb[p] = *(const float4*)(B + (long)(n0 + bn) * ldb + k0 + 4*bkq);
            }
        }
    };
    auto sstore = [&]() {
        #pragma unroll
        for (int p = 0; p < 2; ++p) {
            const int idx = tid + p*T;
            if (OPA == 1) {
                const int ak = idx / (BM/4), amq = idx % (BM/4);
                float4 w = make_float4(tf32r(pa[p].x), tf32r(pa[p].y),
                                       tf32r(pa[p].z), tf32r(pa[p].w));
                *(float4*)&As[ak][4*amq] = w;
            } else {
                const int am = idx / (BK/4), akq = idx % (BK/4);
                As[4*akq+0][am] = tf32r(pa[p].x);
                As[4*akq+1][am] = tf32r(pa[p].y);
                As[4*akq+2][am] = tf32r(pa[p].z);
                As[4*akq+3][am] = tf32r(pa[p].w);
            }
            if (OPB == 1) {
                const int bk = idx / (BN/4), bnq = idx % (BN/4);
                float4 w = make_float4(tf32r(pb[p].x), tf32r(pb[p].y),
                                       tf32r(pb[p].z), tf32r(pb[p].w));
                *(float4*)&Bs[bk][4*bnq] = w;
            } else {
                const int bn = idx / (BK/4), bkq = idx % (BK/4);
                Bs[4*bkq+0][bn] = tf32r(pb[p].x);
                Bs[4*bkq+1][bn] = tf32r(pb[p].y);
                Bs[4*bkq+2][bn] = tf32r(pb[p].z);
                Bs[4*bkq+3][bn] = tf32r(pb[p].w);
            }
        }
    };

    gload(0);
    sstore();
    __syncthreads();

    for (int kt = 0; kt < ktiles; ++kt) {
        const bool more = (kt + 1 < ktiles);
        if (more) gload((kt+1)*BK);

        #pragma unroll
        for (int ks = 0; ks < BK; ks += 8) {
            unsigned af[MT][4], bf[NT][2];
            #pragma unroll
            for (int im = 0; im < MT; ++im) {
                const int mb = mw0 + im*16;
                af[im][0] = __float_as_uint(As[ks+qc  ][mb+qr  ]);
                af[im][1] = __float_as_uint(As[ks+qc  ][mb+qr+8]);
                af[im][2] = __float_as_uint(As[ks+qc+4][mb+qr  ]);
                af[im][3] = __float_as_uint(As[ks+qc+4][mb+qr+8]);
            }
            #pragma unroll
            for (int jn = 0; jn < NT; ++jn) {
                const int nb = nw0 + jn*8;
                bf[jn][0] = __float_as_uint(Bs[ks+qc  ][nb+qr]);
                bf[jn][1] = __float_as_uint(Bs[ks+qc+4][nb+qr]);
            }
            #pragma unroll
            for (int im = 0; im < MT; ++im)
                #pragma unroll
                for (int jn = 0; jn < NT; ++jn)
                    mma_tf32(acc[im][jn], af[im], bf[jn]);
        }
        __syncthreads();
        if (more) { sstore(); __syncthreads(); }
    }

    // epilogue
    #pragma unroll
    for (int im = 0; im < MT; ++im) {
        #pragma unroll
        for (int jn = 0; jn < NT; ++jn) {
            #pragma unroll
            for (int h = 0; h < 2; ++h) {
                const int m = m0 + mw0 + im*16 + qr + h*8;
                const int n = n0 + nw0 + jn*8 + qc*2;
                const long ci = (long)m * ldc + n;
                float v0 = acc[im][jn][h*2 + 0];
                float v1 = acc[im][jn][h*2 + 1];
                if (MODE == 0) {
                    C[ci] = v0; C[ci+1] = v1;
                } else if (MODE == 1) {
                    if (m < RR) {
                        v0 -= P1[(long)m * ldc + n];
                        v1 -= P1[(long)m * ldc + n + 1];
                    }
                    C[ci] = v0; C[ci+1] = v1;
                } else if (MODE == 2) {
                    const bool z = ((n >> 4) > (m >> 4));  // n,n+1 same 16-block
                    C[ci]   = z ? 0.f : v0;
                    C[ci+1] = z ? 0.f : v1;
                } else if (MODE == 3) {
                    C[ci]   = P1[(long)m * DD + n]     - ETA_F * v0;
                    C[ci+1] = P1[(long)m * DD + n + 1] - ETA_F * v1;
                } else if (MODE == 4) {
                    C[ci]   = C[ci]   - ETA_F * v0;
                    C[ci+1] = C[ci+1] - ETA_F * v1;
                } else if (MODE == 5) {
                    C[ci]   = 0.5f * v0 * (1.f + erff(v0 * 0.70710678118654752f));
                    C[ci+1] = 0.5f * v1 * (1.f + erff(v1 * 0.70710678118654752f));
                } else if (MODE == 6) {
                    C[ci]   = P1[ci]   * v0 + P2[ci];
                    C[ci+1] = P1[ci+1] * v1 + P2[ci+1];
                }
            }
        }
    }
}

// ---------------- host side ----------------
extern "C" void kernel_launch(void* const* d_in, const int* in_sizes, int n_in,
                              void* d_out, int out_size) {
    const float* x      = (const float*)d_in[0];
    const float* noise  = (const float*)d_in[1];
    const float* alpha1 = (const float*)d_in[2];
    const float* alpha2 = (const float*)d_in[3];
    const float* W_map  = (const float*)d_in[4];
    const float* W_st   = (const float*)d_in[5];
    const float* W_pr   = (const float*)d_in[6];
    const float* W_p1   = (const float*)d_in[7];
    const float* W_p2   = (const float*)d_in[8];
    float* out = (float*)d_out;

    float *HT, *ST, *TV, *PR, *OT, *X1, *H2, *U, *W, *AP, *E, *Gb, *Hb;
    cudaGetSymbolAddress((void**)&HT, g_HT);
    cudaGetSymbolAddress((void**)&ST, g_STATE);
    cudaGetSymbolAddress((void**)&TV, g_TV);
    cudaGetSymbolAddress((void**)&PR, g_PROBE);
    cudaGetSymbolAddress((void**)&OT, g_OT);
    cudaGetSymbolAddress((void**)&X1, g_X1);
    cudaGetSymbolAddress((void**)&H2, g_H2);
    cudaGetSymbolAddress((void**)&U,  g_U);
    cudaGetSymbolAddress((void**)&W,  g_W);
    cudaGetSymbolAddress((void**)&AP, g_AP);
    cudaGetSymbolAddress((void**)&E,  g_E);
    cudaGetSymbolAddress((void**)&Gb, g_Gb);
    cudaGetSymbolAddress((void**)&Hb, g_Hb);

    const int EW_BLKS = (SB*DD/4) / 256;

    // 1. h = tanh(alpha1*x), time-major
    k_prep<<<EW_BLKS, 256>>>(x, alpha1, HT);
    // 2. STATE / PROBE big GEMMs (tensor cores)
    gemm_t<128,128,2,4,0,0,0><<<dim3(DD/128, SB/128, 1), 256>>>(
        HT, nullptr, DD, W_st, DD, ST, DD, SB, DD, DD, nullptr, nullptr, 0,0,0);
    gemm_t<128,128,2,4,0,0,0><<<dim3(DD/128, SB/128, 1), 256>>>(
        HT, nullptr, DD, W_pr, DD, PR, DD, SB, DD, DD, nullptr, nullptr, 0,0,0);
    // 3. TV = STATE + noise
    k_tv<<<EW_BLKS, 256>>>(ST, noise, TV);
    // 4. W = W_map
    k_copyW<<<(DD*DD/4)/256, 256>>>(W_map, W);
    // 5. batched Gram + masked cross-Gram
    gemm_t<64,64,2,2,0,0,0><<<dim3(RR/64, RR/64, NC), 128>>>(
        TV, nullptr, DD, TV, DD, Gb, RR, RR, RR, DD, nullptr, nullptr,
        (long)RR*DD, (long)RR*DD, (long)RR*RR);
    gemm_t<64,64,2,2,0,0,2><<<dim3(RR/64, RR/64, NC), 128>>>(
        PR, nullptr, DD, TV, DD, Hb, RR, RR, RR, DD, nullptr, nullptr,
        (long)RR*DD, (long)RR*DD, (long)RR*RR);

    // 6. sequential chunk loop
    for (int c = 0; c < NC; ++c) {
        const float* TVc = TV + (long)c*RR*DD;
        const float* PRc = PR + (long)c*RR*DD;
        const float* STc = ST + (long)c*RR*DD;
        // A = TVc@W^T - STATEc (rows<RR) ; P0 = PRc@W^T (rows>=RR)
        gemm_t<64,64,2,2,2,0,1><<<dim3(DD/64, (2*RR)/64, 1), 128>>>(
            TVc, PRc, DD, W, DD, AP, DD, 2*RR, DD, DD, STc, nullptr, 0,0,0);
        // forward substitution -> E
        solve_k<<<DD/16, 256>>>(AP, Gb + (long)c*RR*RR, E);
        // readout = P0 - ETA * trilH @ E
        gemm_t<64,64,2,2,0,1,3><<<dim3(DD/64, RR/64, 1), 128>>>(
            Hb + (long)c*RR*RR, nullptr, RR, E, DD,
            OT + (long)c*RR*DD, DD, RR, DD, RR,
            AP + (long)RR*DD, nullptr, 0,0,0);
        // W -= ETA * E^T @ TVc
        gemm_t<64,64,2,2,1,1,4><<<dim3(DD/64, DD/64, 1), 128>>>(
            E, nullptr, DD, TVc, DD, W, DD, DD, DD, RR, nullptr, nullptr, 0,0,0);
    }

    // 7. x1 / h2
    k_x1h2<<<EW_BLKS, 256>>>(OT, x, alpha2, X1, H2);
    // 8. U = gelu(h2 @ Wp1^T)
    gemm_t<128,128,2,4,0,0,5><<<dim3(DD/128, SB/128, 1), 256>>>(
        H2, nullptr, DD, W_p1, DD, U, DD, SB, DD, DD, nullptr, nullptr, 0,0,0);
    // 9. out = U * (h2 @ Wp2^T) + X1
    gemm_t<128,128,2,4,0,0,6><<<dim3(DD/128, SB/128, 1), 256>>>(
        H2, nullptr, DD, W_p2, DD, out, DD, SB, DD, DD, U, X1, 0,0,0);
}

// round 4
// speedup vs baseline: 1.3673x; 1.0423x over previous
#include <cuda_runtime.h>
#include <math.h>

#define BB 16
#define SS 1024
#define DD 1024
#define CH 32
#define RR 512            // CH*BB rows per chunk
#define NC 32             // SS/CH chunks
#define SB (SS*BB)        // 16384 rows total
#define CSTEPS (RR/16)    // 32 sequential steps per chunk
#define ETA_F (0.01f*2.0f/(16.0f*1024.0f))

// ---------------- device scratch ----------------
__device__ float g_HT[SB*DD];
__device__ float g_STATE[SB*DD];
__device__ float g_TV[SB*DD];
__device__ float g_PROBE[SB*DD];
__device__ float g_OT[SB*DD];
__device__ float g_X1[SB*DD];
__device__ float g_H2[SB*DD];
__device__ float g_U[SB*DD];
__device__ float g_W[DD*DD];
__device__ float g_AP[2*RR*DD];
__device__ float g_E[RR*DD];
__device__ float g_Gb[NC*RR*RR];
__device__ float g_Hb[NC*RR*RR];

// ---------------- helpers ----------------
__device__ __forceinline__ float tf32r(float x) {
    unsigned u;
    asm("cvt.rna.tf32.f32 %0, %1;" : "=r"(u) : "f"(x));
    return __uint_as_float(u);
}

__device__ __forceinline__ void mma_tf32(float* c, const unsigned* a, const unsigned* b) {
    asm volatile(
        "mma.sync.aligned.m16n8k8.row.col.f32.tf32.tf32.f32 "
        "{%0,%1,%2,%3}, {%4,%5,%6,%7}, {%8,%9}, {%0,%1,%2,%3};\n"
        : "+f"(c[0]), "+f"(c[1]), "+f"(c[2]), "+f"(c[3])
        : "r"(a[0]), "r"(a[1]), "r"(a[2]), "r"(a[3]), "r"(b[0]), "r"(b[1]));
}

__device__ __forceinline__ void ldsm4(unsigned& r0, unsigned& r1, unsigned& r2,
                                      unsigned& r3, unsigned addr) {
    asm volatile("ldmatrix.sync.aligned.m8n8.x4.shared.b16 {%0,%1,%2,%3},[%4];"
                 : "=r"(r0), "=r"(r1), "=r"(r2), "=r"(r3) : "r"(addr));
}

// ---------------- elementwise kernels ----------------
__global__ void k_prep(const float* __restrict__ x, const float* __restrict__ a1,
                       float* __restrict__ HT) {
    long i4 = (long)blockIdx.x * blockDim.x + threadIdx.x;
    long flat = i4 * 4;
    int b = (int)(flat / ((long)SS*DD));
    int t = (int)((flat / DD) % SS);
    int d = (int)(flat % DD);
    float4 xv = *(const float4*)(x + flat);
    float4 av = *(const float4*)(a1 + d);
    float4 o;
    o.x = tanhf(av.x * xv.x); o.y = tanhf(av.y * xv.y);
    o.z = tanhf(av.z * xv.z); o.w = tanhf(av.w * xv.w);
    *(float4*)(HT + ((long)(t*BB + b) * DD + d)) = o;
}

__global__ void k_tv(const float* __restrict__ ST, const float* __restrict__ noise,
                     float* __restrict__ TV) {
    long i4 = (long)blockIdx.x * blockDim.x + threadIdx.x;
    long flat = i4 * 4;
    int t = (int)(flat / ((long)BB*DD));
    int b = (int)((flat / DD) % BB);
    int d = (int)(flat % DD);
    float4 s = *(const float4*)(ST + flat);
    float4 n = *(const float4*)(noise + ((long)b*SS + t) * DD + d);
    float4 o; o.x = s.x+n.x; o.y = s.y+n.y; o.z = s.z+n.z; o.w = s.w+n.w;
    *(float4*)(TV + flat) = o;
}

__global__ void k_copyW(const float* __restrict__ src, float* __restrict__ dst) {
    long i4 = (long)blockIdx.x * blockDim.x + threadIdx.x;
    *(float4*)(dst + i4*4) = *(const float4*)(src + i4*4);
}

__global__ void k_x1h2(const float* __restrict__ OT, const float* __restrict__ x,
                       const float* __restrict__ a2,
                       float* __restrict__ X1, float* __restrict__ H2) {
    long i4 = (long)blockIdx.x * blockDim.x + threadIdx.x;
    long flat = i4 * 4;
    int b = (int)(flat / ((long)SS*DD));
    int t = (int)((flat / DD) % SS);
    int d = (int)(flat % DD);
    float4 ro = *(const float4*)(OT + ((long)(t*BB + b) * DD + d));
    float4 xv = *(const float4*)(x + flat);
    float4 av = *(const float4*)(a2 + d);
    float4 x1; x1.x = ro.x+xv.x; x1.y = ro.y+xv.y; x1.z = ro.z+xv.z; x1.w = ro.w+xv.w;
    *(float4*)(X1 + flat) = x1;
    float4 h; h.x = tanhf(av.x*x1.x); h.y = tanhf(av.y*x1.y);
    h.z = tanhf(av.z*x1.z); h.w = tanhf(av.w*x1.w);
    *(float4*)(H2 + flat) = h;
}

// ---------------- forward substitution (RR=512, 32 steps) ----------------
// Es layout: [j][row]  (column-major per CTA's 16 columns) -> float4 LDS along k
__global__ void __launch_bounds__(256) solve_k(const float* __restrict__ A,
                                               const float* __restrict__ G,
                                               float* __restrict__ E) {
    __shared__ __align__(16) float Es[16][RR + 4];   // row stride 516 floats (16B mult)
    const int j0 = blockIdx.x * 16;
    const int tid = threadIdx.x;
    const int r = tid >> 4, j = tid & 15;
    #pragma unroll
    for (int i = 0; i < CSTEPS; ++i) {
        int row = i*16 + r;
        Es[j][row] = A[(long)row * DD + j0 + j];
    }
    __syncthreads();
    for (int t = 1; t < CSTEPS; ++t) {
        const int row = t*16 + r;
        const float* Gr = G + (long)row * RR;
        const int kmax = t * 16;
        float sx=0.f, sy=0.f, sz=0.f, sw=0.f;
        for (int k = 0; k < kmax; k += 4) {
            float4 g = *(const float4*)(Gr + k);
            float4 e = *(const float4*)&Es[j][k];
            sx = fmaf(g.x, e.x, sx); sy = fmaf(g.y, e.y, sy);
            sz = fmaf(g.z, e.z, sz); sw = fmaf(g.w, e.w, sw);
        }
        float v = Es[j][row] - ETA_F * ((sx+sy)+(sz+sw));
        Es[j][row] = v;   // row >= kmax: disjoint from this step's reads
        __syncthreads();
    }
    #pragma unroll
    for (int i = 0; i < CSTEPS; ++i) {
        int row = i*16 + r;
        E[(long)row * DD + j0 + j] = Es[j][row];
    }
}

// ---------------- tf32 tensor-core GEMM (ldmatrix + double buffer) ----------
// OPA: 0 = A[M,K] row-major; 1 = A stored [K,M]; 2 = dual-source rows
// OPB: 0 = C = A*B^T, B[N,K]; 1 = C = A*B, B[K,N]
// MODE: 0 plain  1 sub P1 on rows<RR  2 block-tril mask (+skip upper tiles)
//       3 C=P1-ETA*acc (tril-K)  4 C-=ETA*acc  5 gelu  6 C=P1*acc+P2
template<int BM,int BN,int MW,int NW,int OPA,int OPB,int MODE>
__global__ void __launch_bounds__(MW*NW*32, (MW*NW*32==256) ? 2 : 3)
gemm_t(const float* __restrict__ A, const float* __restrict__ A2, int lda,
       const float* __restrict__ B, int ldb,
       float* __restrict__ C, int ldc,
       int M, int N, int K,
       const float* __restrict__ P1, const float* __restrict__ P2,
       long saz, long sbz, long scz)
{
    constexpr int BK  = 16;
    constexpr int BKp = 20;                 // row pad: conflict-free LDSM, 16B-mult rows
    constexpr int T   = MW*NW*32;
    constexpr int WM  = BM/MW, WN = BN/NW;
    constexpr int MT  = WM/16, NT = WN/8;
    constexpr int LPA = BM*BK/(4*T);
    constexpr int LPB = BN*BK/(4*T);

    const int m0 = blockIdx.y * BM, n0 = blockIdx.x * BN;
    if (MODE == 2 && n0 >= m0 + BM) return;     // strictly-upper tile: never read

    const int bz = blockIdx.z;
    A += (long)bz * saz;
    B += (long)bz * sbz;
    C += (long)bz * scz;

    __shared__ __align__(16) float As[2][BM][BKp];
    __shared__ __align__(16) float Bs[2][BN][BKp];

    const int tid  = threadIdx.x;
    const int lane = tid & 31;
    const int wid  = tid >> 5;
    const int wm   = wid / NW, wn = wid % NW;
    const int mw0  = wm * WM, nw0 = wn * WN;
    const int qr   = lane >> 2;
    const int qc   = lane & 3;
    const int lr   = lane & 7;
    // ldmatrix per-lane bases (element offsets into the [.][BKp] plane)
    const int aBase = (mw0 + lr + ((lane>>3)&1)*8) * BKp + ((lane>>4)&1)*4;
    const int bBase = (nw0 + lr + ((lane>>4)&1)*8) * BKp + ((lane>>3)&1)*4;

    float acc[MT][NT][4];
    #pragma unroll
    for (int i = 0; i < MT; ++i)
        #pragma unroll
        for (int j = 0; j < NT; ++j)
            #pragma unroll
            for (int q = 0; q < 4; ++q) acc[i][j][q] = 0.f;

    int Kl = K;
    if (MODE == 3) { int kl = m0 + BM; Kl = kl < K ? kl : K; }
    const int ktiles = Kl / BK;

    float4 pa[LPA], pb[LPB];

    auto gload = [&](int k0) {
        #pragma unroll
        for (int p = 0; p < LPA; ++p) {
            const int idx = tid + p*T;
            if (OPA == 1) {
                const int ak = idx / (BM/4), amq = idx % (BM/4);
                pa[p] = *(const float4*)(A + (long)(k0 + ak) * lda + m0 + 4*amq);
            } else {
                const int am = idx / (BK/4), akq = idx % (BK/4);
                const int mg = m0 + am;
                const float* Ar;
                if (OPA == 2) Ar = (mg < RR) ? (A + (long)mg * lda)
                                             : (A2 + (long)(mg - RR) * lda);
                else          Ar = A + (long)mg * lda;
                pa[p] = *(const float4*)(Ar + k0 + 4*akq);
            }
        }
        #pragma unroll
        for (int p = 0; p < LPB; ++p) {
            const int idx = tid + p*T;
            if (OPB == 1) {
                const int bk = idx / (BN/4), bnq = idx % (BN/4);
                pb[p] = *(const float4*)(B + (long)(k0 + bk) * ldb + n0 + 4*bnq);
            } else {
                const int bn = idx / (BK/4), bkq = idx % (BK/4);
                pb[p] = *(const float4*)(B + (long)(n0 + bn) * ldb + k0 + 4*bkq);
            }
        }
    };
    auto sstore = [&](int s) {
        #pragma unroll
        for (int p = 0; p < LPA; ++p) {
            const int idx = tid + p*T;
            if (OPA == 1) {
                const int ak = idx / (BM/4), amq = idx % (BM/4);
                As[s][4*amq+0][ak] = tf32r(pa[p].x);
                As[s][4*amq+1][ak] = tf32r(pa[p].y);
                As[s][4*amq+2][ak] = tf32r(pa[p].z);
                As[s][4*amq+3][ak] = tf32r(pa[p].w);
            } else {
                const int am = idx / (BK/4), akq = idx % (BK/4);
                float4 w = make_float4(tf32r(pa[p].x), tf32r(pa[p].y),
                                       tf32r(pa[p].z), tf32r(pa[p].w));
                *(float4*)&As[s][am][4*akq] = w;
            }
        }
        #pragma unroll
        for (int p = 0; p < LPB; ++p) {
            const int idx = tid + p*T;
            if (OPB == 1) {
                const int bk = idx / (BN/4), bnq = idx % (BN/4);
                Bs[s][4*bnq+0][bk] = tf32r(pb[p].x);
                Bs[s][4*bnq+1][bk] = tf32r(pb[p].y);
                Bs[s][4*bnq+2][bk] = tf32r(pb[p].z);
                Bs[s][4*bnq+3][bk] = tf32r(pb[p].w);
            } else {
                const int bn = idx / (BK/4), bkq = idx % (BK/4);
                float4 w = make_float4(tf32r(pb[p].x), tf32r(pb[p].y),
                                       tf32r(pb[p].z), tf32r(pb[p].w));
                *(float4*)&Bs[s][bn][4*bkq] = w;
            }
        }
    };
    auto compute = [&](int s) {
        const unsigned sA = (unsigned)__cvta_generic_to_shared(&As[s][0][0]);
        const unsigned sB = (unsigned)__cvta_generic_to_shared(&Bs[s][0][0]);
        #pragma unroll
        for (int ks = 0; ks < BK; ks += 8) {
            unsigned af[MT][4];
            #pragma unroll
            for (int im = 0; im < MT; ++im)
                ldsm4(af[im][0], af[im][1], af[im][2], af[im][3],
                      sA + 4u*(aBase + im*16*BKp + ks));
            unsigned bf[NT][2];
            #pragma unroll
            for (int jp = 0; jp < NT/2; ++jp) {
                unsigned r0, r1, r2, r3;
                ldsm4(r0, r1, r2, r3, sB + 4u*(bBase + jp*16*BKp + ks));
                bf[2*jp][0] = r0; bf[2*jp][1] = r1;
                bf[2*jp+1][0] = r2; bf[2*jp+1][1] = r3;
            }
            #pragma unroll
            for (int im = 0; im < MT; ++im)
                #pragma unroll
                for (int jn = 0; jn < NT; ++jn)
                    mma_tf32(acc[im][jn], af[im], bf[jn]);
        }
    };

    gload(0);
    sstore(0);
    __syncthreads();

    for (int kt = 0; kt < ktiles; ++kt) {
        const bool more = (kt + 1 < ktiles);
        if (more) gload((kt+1)*BK);
        compute(kt & 1);
        if (more) sstore((kt+1) & 1);
        __syncthreads();
    }

    // epilogue
    #pragma unroll
    for (int im = 0; im < MT; ++im) {
        #pragma unroll
        for (int jn = 0; jn < NT; ++jn) {
            #pragma unroll
            for (int h = 0; h < 2; ++h) {
                const int m = m0 + mw0 + im*16 + qr + h*8;
                const int n = n0 + nw0 + jn*8 + qc*2;
                const long ci = (long)m * ldc + n;
                float v0 = acc[im][jn][h*2 + 0];
                float v1 = acc[im][jn][h*2 + 1];
                if (MODE == 0) {
                    C[ci] = v0; C[ci+1] = v1;
                } else if (MODE == 1) {
                    if (m < RR) {
                        v0 -= P1[(long)m * ldc + n];
                        v1 -= P1[(long)m * ldc + n + 1];
                    }
                    C[ci] = v0; C[ci+1] = v1;
                } else if (MODE == 2) {
                    const bool z = ((n >> 4) > (m >> 4));
                    C[ci]   = z ? 0.f : v0;
                    C[ci+1] = z ? 0.f : v1;
                } else if (MODE == 3) {
                    C[ci]   = P1[(long)m * DD + n]     - ETA_F * v0;
                    C[ci+1] = P1[(long)m * DD + n + 1] - ETA_F * v1;
                } else if (MODE == 4) {
                    C[ci]   = C[ci]   - ETA_F * v0;
                    C[ci+1] = C[ci+1] - ETA_F * v1;
                } else if (MODE == 5) {
                    C[ci]   = 0.5f * v0 * (1.f + erff(v0 * 0.70710678118654752f));
                    C[ci+1] = 0.5f * v1 * (1.f + erff(v1 * 0.70710678118654752f));
                } else if (MODE == 6) {
                    C[ci]   = P1[ci]   * v0 + P2[ci];
                    C[ci+1] = P1[ci+1] * v1 + P2[ci+1];
                }
            }
        }
    }
}

// ---------------- host side ----------------
extern "C" void kernel_launch(void* const* d_in, const int* in_sizes, int n_in,
                              void* d_out, int out_size) {
    const float* x      = (const float*)d_in[0];
    const float* noise  = (const float*)d_in[1];
    const float* alpha1 = (const float*)d_in[2];
    const float* alpha2 = (const float*)d_in[3];
    const float* W_map  = (const float*)d_in[4];
    const float* W_st   = (const float*)d_in[5];
    const float* W_pr   = (const float*)d_in[6];
    const float* W_p1   = (const float*)d_in[7];
    const float* W_p2   = (const float*)d_in[8];
    float* out = (float*)d_out;

    float *HT, *ST, *TV, *PR, *OT, *X1, *H2, *U, *W, *AP, *E, *Gb, *Hb;
    cudaGetSymbolAddress((void**)&HT, g_HT);
    cudaGetSymbolAddress((void**)&ST, g_STATE);
    cudaGetSymbolAddress((void**)&TV, g_TV);
    cudaGetSymbolAddress((void**)&PR, g_PROBE);
    cudaGetSymbolAddress((void**)&OT, g_OT);
    cudaGetSymbolAddress((void**)&X1, g_X1);
    cudaGetSymbolAddress((void**)&H2, g_H2);
    cudaGetSymbolAddress((void**)&U,  g_U);
    cudaGetSymbolAddress((void**)&W,  g_W);
    cudaGetSymbolAddress((void**)&AP, g_AP);
    cudaGetSymbolAddress((void**)&E,  g_E);
    cudaGetSymbolAddress((void**)&Gb, g_Gb);
    cudaGetSymbolAddress((void**)&Hb, g_Hb);

    const int EW_BLKS = (SB*DD/4) / 256;

    // 1. h = tanh(alpha1*x), time-major
    k_prep<<<EW_BLKS, 256>>>(x, alpha1, HT);
    // 2. STATE / PROBE big GEMMs
    gemm_t<128,128,2,4,0,0,0><<<dim3(DD/128, SB/128, 1), 256>>>(
        HT, nullptr, DD, W_st, DD, ST, DD, SB, DD, DD, nullptr, nullptr, 0,0,0);
    gemm_t<128,128,2,4,0,0,0><<<dim3(DD/128, SB/128, 1), 256>>>(
        HT, nullptr, DD, W_pr, DD, PR, DD, SB, DD, DD, nullptr, nullptr, 0,0,0);
    // 3. TV = STATE + noise
    k_tv<<<EW_BLKS, 256>>>(ST, noise, TV);
    // 4. W = W_map
    k_copyW<<<(DD*DD/4)/256, 256>>>(W_map, W);
    // 5. batched block-tril Gram + cross-Gram (upper tiles skipped)
    gemm_t<64,64,2,2,0,0,2><<<dim3(RR/64, RR/64, NC), 128>>>(
        TV, nullptr, DD, TV, DD, Gb, RR, RR, RR, DD, nullptr, nullptr,
        (long)RR*DD, (long)RR*DD, (long)RR*RR);
    gemm_t<64,64,2,2,0,0,2><<<dim3(RR/64, RR/64, NC), 128>>>(
        PR, nullptr, DD, TV, DD, Hb, RR, RR, RR, DD, nullptr, nullptr,
        (long)RR*DD, (long)RR*DD, (long)RR*RR);

    // 6. sequential chunk loop (32 chunks)
    for (int c = 0; c < NC; ++c) {
        const float* TVc = TV + (long)c*RR*DD;
        const float* PRc = PR + (long)c*RR*DD;
        const float* STc = ST + (long)c*RR*DD;
        // A = TVc@W^T - STATEc (rows<RR) ; P0 = PRc@W^T (rows>=RR)
        gemm_t<64,64,2,2,2,0,1><<<dim3(DD/64, (2*RR)/64, 1), 128>>>(
            TVc, PRc, DD, W, DD, AP, DD, 2*RR, DD, DD, STc, nullptr, 0,0,0);
        // forward substitution -> E
        solve_k<<<DD/16, 256>>>(AP, Gb + (long)c*RR*RR, E);
        // readout = P0 - ETA * trilH @ E
        gemm_t<64,64,2,2,0,1,3><<<dim3(DD/64, RR/64, 1), 128>>>(
            Hb + (long)c*RR*RR, nullptr, RR, E, DD,
            OT + (long)c*RR*DD, DD, RR, DD, RR,
            AP + (long)RR*DD, nullptr, 0,0,0);
        // W -= ETA * E^T @ TVc
        gemm_t<64,64,2,2,1,1,4><<<dim3(DD/64, DD/64, 1), 128>>>(
            E, nullptr, DD, TVc, DD, W, DD, DD, DD, RR, nullptr, nullptr, 0,0,0);
    }

    // 7. x1 / h2
    k_x1h2<<<EW_BLKS, 256>>>(OT, x, alpha2, X1, H2);
    // 8. U = gelu(h2 @ Wp1^T)
    gemm_t<128,128,2,4,0,0,5><<<dim3(DD/128, SB/128, 1), 256>>>(
        H2, nullptr, DD, W_p1, DD, U, DD, SB, DD, DD, nullptr, nullptr, 0,0,0);
    // 9. out = U * (h2 @ Wp2^T) + X1
    gemm_t<128,128,2,4,0,0,6><<<dim3(DD/128, SB/128, 1), 256>>>(
        H2, nullptr, DD, W_p2, DD, out, DD, SB, DD, DD, U, X1, 0,0,0);
}